// round 15
// baseline (speedup 1.0000x reference)
#include <cuda_runtime.h>
#include <cstdint>

typedef uint32_t u32;
typedef unsigned long long u64;

__device__ __forceinline__ u32 pkbf(float lo, float hi) {
    u32 r; asm("cvt.rn.bf16x2.f32 %0, %1, %2;" : "=r"(r) : "f"(hi), "f"(lo)); return r;
}
__device__ __forceinline__ float bflo(u32 h) { return __uint_as_float(h << 16); }
__device__ __forceinline__ float bfhi(u32 h) { return __uint_as_float(h & 0xFFFF0000u); }

__device__ __forceinline__ u64 pk64(float lo, float hi) {
    u64 r; asm("mov.b64 %0, {%1, %2};" : "=l"(r) : "f"(lo), "f"(hi)); return r;
}
__device__ __forceinline__ u64 pk64u(u32 lo, u32 hi) {
    u64 r; asm("mov.b64 %0, {%1, %2};" : "=l"(r) : "r"(lo), "r"(hi)); return r;
}
__device__ __forceinline__ void up64(float& lo, float& hi, u64 v) {
    asm("mov.b64 {%0, %1}, %2;" : "=f"(lo), "=f"(hi) : "l"(v));
}
#define ADD2(d, a, b)    asm("add.rn.f32x2 %0, %1, %2;"     : "=l"(d) : "l"(a), "l"(b))
#define MUL2(d, a, b)    asm("mul.rn.f32x2 %0, %1, %2;"     : "=l"(d) : "l"(a), "l"(b))
#define FMA2(d, a, b, c) asm("fma.rn.f32x2 %0, %1, %2, %3;" : "=l"(d) : "l"(a), "l"(b), "l"(c))

#define NEG1X2  0xBF800000BF800000ull   // (-1.0f, -1.0f)
#define C001X2  0x3C23D70A3C23D70Aull   // (0.01f, 0.01f)

// prep-side split (scalar, runs once)
__device__ __forceinline__ void split2_prep(float a, float b, u32& hp, u32& lp) {
    hp = pkbf(a, b);
    lp = pkbf(a - bflo(hp), b - bfhi(hp));
}

// hot-loop split: residual pair via one packed FMA (identical rounding to scalar subs)
__device__ __forceinline__ void split2(float a, float b, u32& hp, u32& lp) {
    hp = pkbf(a, b);
    const u64 hv = pk64u(hp << 16, hp & 0xFFFF0000u);
    const u64 ab = pk64(a, b);
    u64 res;
    const u64 neg1 = NEG1X2;
    FMA2(res, hv, neg1, ab);
    float rl, rh; up64(rl, rh, res);
    lp = pkbf(rl, rh);
}

#define MMA(d, a0, a1, a2, a3, b0, b1)                                      \
    asm volatile("mma.sync.aligned.m16n8k16.row.col.f32.bf16.bf16.f32 "     \
                 "{%0,%1,%2,%3},{%4,%5,%6,%7},{%8,%9},{%0,%1,%2,%3};"       \
                 : "+f"((d)[0]), "+f"((d)[1]), "+f"((d)[2]), "+f"((d)[3])   \
                 : "r"(a0), "r"(a1), "r"(a2), "r"(a3), "r"(b0), "r"(b1))

// Per-lane weight fragments: uint4 = {hi_b0, hi_b1, lo_b0, lo_b1}
struct __align__(16) WBlob {
    uint4 w1[4][4][32];
    uint4 w2[2][4][32];
    uint4 w3[2][8][32];
    float ab[32], cb[32], bo[64];
    float l1g[32], l1b[32], l2g[32], l2b[32];
};
__device__ WBlob g_wp;

// ---------------- prep (identical to R6/R14) ----------------
__global__ void prep_kernel(
    const float* __restrict__ w1,  const float* __restrict__ b1,
    const float* __restrict__ wv1, const float* __restrict__ bv1, const float* __restrict__ g1,
    const float* __restrict__ l1g, const float* __restrict__ l1b,
    const float* __restrict__ w2,  const float* __restrict__ b2,
    const float* __restrict__ wv2, const float* __restrict__ bv2, const float* __restrict__ g2,
    const float* __restrict__ l2g, const float* __restrict__ l2b,
    const float* __restrict__ wo,  const float* __restrict__ bo)
{
    __shared__ float Af[64 * 32];
    __shared__ float Cf[32 * 32];
    const int t = threadIdx.x;
    const float g1v = g1[0], g2v = g2[0];

    for (int idx = t; idx < 64 * 32; idx += blockDim.x) {
        int i = idx >> 5, j = idx & 31;
        float s = 0.f;
        for (int m = 0; m < 32; m++) s += w1[i * 32 + m] * wv1[m * 32 + j];
        Af[idx] = w1[i * 32 + j] + g1v * s;
    }
    for (int idx = t; idx < 32 * 32; idx += blockDim.x) {
        int i = idx >> 5, j = idx & 31;
        float s = 0.f;
        for (int m = 0; m < 32; m++) s += w2[i * 32 + m] * wv2[m * 32 + j];
        Cf[idx] = w2[i * 32 + j] + g2v * s;
    }
    __syncthreads();

    for (int idx = t; idx < 4 * 4 * 32; idx += blockDim.x) {
        int kk = idx >> 7, nn = (idx >> 5) & 3, ln = idx & 31;
        int gg = ln >> 2, tt = ln & 3;
        int kb = 16 * kk + 4 * tt, n = 8 * nn + gg;
        float a0 = Af[kb * 32 + n],       a1 = Af[(kb + 1) * 32 + n];
        float a2 = Af[(kb + 2) * 32 + n], a3 = Af[(kb + 3) * 32 + n];
        uint4 v;
        split2_prep(a0, a1, v.x, v.z);
        split2_prep(a2, a3, v.y, v.w);
        g_wp.w1[kk][nn][ln] = v;
    }
    for (int idx = t; idx < 2 * 4 * 32; idx += blockDim.x) {
        int kk = idx >> 7, nn = (idx >> 5) & 3, ln = idx & 31;
        int gg = ln >> 2, tt = ln & 3;
        int k0 = 16 * kk + 2 * tt, n = 8 * nn + gg;
        float a0 = Cf[k0 * 32 + n],       a1 = Cf[(k0 + 1) * 32 + n];
        float a2 = Cf[(k0 + 8) * 32 + n], a3 = Cf[(k0 + 9) * 32 + n];
        uint4 v;
        split2_prep(a0, a1, v.x, v.z);
        split2_prep(a2, a3, v.y, v.w);
        g_wp.w2[kk][nn][ln] = v;
    }
    for (int idx = t; idx < 2 * 8 * 32; idx += blockDim.x) {
        int kk = idx >> 8, nn = (idx >> 5) & 7, ln = idx & 31;
        int gg = ln >> 2, tt = ln & 3;
        int k0 = 16 * kk + 2 * tt;
        int c = 16 * (nn >> 1) + 4 * (gg >> 1) + 2 * (nn & 1) + (gg & 1);
        float a0 = wo[k0 * 64 + c],       a1 = wo[(k0 + 1) * 64 + c];
        float a2 = wo[(k0 + 8) * 64 + c], a3 = wo[(k0 + 9) * 64 + c];
        uint4 v;
        split2_prep(a0, a1, v.x, v.z);
        split2_prep(a2, a3, v.y, v.w);
        g_wp.w3[kk][nn][ln] = v;
    }
    if (t < 32) {
        int j = t;
        float s1 = 0.f, s2 = 0.f;
        for (int m = 0; m < 32; m++) {
            s1 += b1[m] * wv1[m * 32 + j];
            s2 += b2[m] * wv2[m * 32 + j];
        }
        g_wp.ab[j] = b1[j] + g1v * (s1 + bv1[j]);
        g_wp.cb[j] = b2[j] + g2v * (s2 + bv2[j]);
        g_wp.l1g[j] = l1g[j]; g_wp.l1b[j] = l1b[j];
        g_wp.l2g[j] = l2g[j]; g_wp.l2b[j] = l2b[j];
    }
    if (t < 64) g_wp.bo[t] = bo[t];
}

// bias + LN + leaky on [16 x 32] block, f32x2-packed throughout
__device__ __forceinline__ void ln_block(float acc[4][4],
                                         const float* __restrict__ bias,
                                         const float* __restrict__ gg,
                                         const float* __restrict__ bb,
                                         int t, u32 oh[2][4], u32 ol[2][4])
{
    u64 p0[4], p1[4];
#pragma unroll
    for (int nn = 0; nn < 4; nn++) {
        const u64 bv = *(const u64*)(bias + 8 * nn + 2 * t);
        u64 a0 = pk64(acc[nn][0], acc[nn][1]);
        u64 a1 = pk64(acc[nn][2], acc[nn][3]);
        ADD2(p0[nn], a0, bv);
        ADD2(p1[nn], a1, bv);
    }
    u64 S0, S1, T0, T1, Q0, Q1;
    ADD2(S0, p0[0], p0[1]); ADD2(T0, p0[2], p0[3]); ADD2(S0, S0, T0);
    ADD2(S1, p1[0], p1[1]); ADD2(T1, p1[2], p1[3]); ADD2(S1, S1, T1);
    MUL2(Q0, p0[0], p0[0]); FMA2(Q0, p0[1], p0[1], Q0);
    FMA2(Q0, p0[2], p0[2], Q0); FMA2(Q0, p0[3], p0[3], Q0);
    MUL2(Q1, p1[0], p1[0]); FMA2(Q1, p1[1], p1[1], Q1);
    FMA2(Q1, p1[2], p1[2], Q1); FMA2(Q1, p1[3], p1[3], Q1);
    float al, ah, bl, bh;
    up64(al, ah, S0); float s0 = al + ah;
    up64(bl, bh, S1); float s1 = bl + bh;
    up64(al, ah, Q0); float q0 = al + ah;
    up64(bl, bh, Q1); float q1 = bl + bh;
#pragma unroll
    for (int m = 1; m < 4; m <<= 1) {
        s0 += __shfl_xor_sync(0xffffffffu, s0, m, 4);
        q0 += __shfl_xor_sync(0xffffffffu, q0, m, 4);
        s1 += __shfl_xor_sync(0xffffffffu, s1, m, 4);
        q1 += __shfl_xor_sync(0xffffffffu, q1, m, 4);
    }
    const float c = 1.0f / 32.0f;
    const float m0 = s0 * c, r0 = rsqrtf(fmaf(-m0, m0, q0 * c) + 1e-5f);
    const float m1 = s1 * c, r1 = rsqrtf(fmaf(-m1, m1, q1 * c) + 1e-5f);
    const u64 R0 = pk64(r0, r0), C0 = pk64(-m0 * r0, -m0 * r0);
    const u64 R1 = pk64(r1, r1), C1 = pk64(-m1 * r1, -m1 * r1);
    const u64 c001 = C001X2;

    float y[4][4];
#pragma unroll
    for (int nn = 0; nn < 4; nn++) {
        const u64 gv = *(const u64*)(gg + 8 * nn + 2 * t);
        const u64 bv = *(const u64*)(bb + 8 * nn + 2 * t);
        u64 n0, n1, y0, y1, z0, z1;
        FMA2(n0, p0[nn], R0, C0);
        FMA2(y0, n0, gv, bv);
        FMA2(n1, p1[nn], R1, C1);
        FMA2(y1, n1, gv, bv);
        MUL2(z0, y0, c001);
        MUL2(z1, y1, c001);
        float a, b, za, zb;
        up64(a, b, y0); up64(za, zb, z0);
        y[nn][0] = fmaxf(a, za); y[nn][1] = fmaxf(b, zb);
        up64(a, b, y1); up64(za, zb, z1);
        y[nn][2] = fmaxf(a, za); y[nn][3] = fmaxf(b, zb);
    }
#pragma unroll
    for (int kk = 0; kk < 2; kk++) {
        split2(y[2 * kk][0],     y[2 * kk][1],     oh[kk][0], ol[kk][0]);
        split2(y[2 * kk][2],     y[2 * kk][3],     oh[kk][1], ol[kk][1]);
        split2(y[2 * kk + 1][0], y[2 * kk + 1][1], oh[kk][2], ol[kk][2]);
        split2(y[2 * kk + 1][2], y[2 * kk + 1][3], oh[kk][3], ol[kk][3]);
    }
}

__device__ __forceinline__ void loadx(const float* __restrict__ x, int tile, int g, int t,
                                      int nrows, float4 xa[4], float4 xb[4])
{
    const int r0 = tile * 16 + g, r1 = r0 + 8;
    const float* b0 = x + (size_t)r0 * 64 + 4 * t;
    const float* b1 = x + (size_t)r1 * 64 + 4 * t;
    const bool v0 = r0 < nrows, v1 = r1 < nrows;
#pragma unroll
    for (int kk = 0; kk < 4; kk++) {
        xa[kk] = v0 ? __ldcs((const float4*)(b0 + 16 * kk)) : make_float4(0.f, 0.f, 0.f, 0.f);
        xb[kk] = v1 ? __ldcs((const float4*)(b1 + 16 * kk)) : make_float4(0.f, 0.f, 0.f, 0.f);
    }
}

// ---------------- fused kernel: R14 body + packed split/leaky/bias ----------------
__global__ void __launch_bounds__(128, 3)
fused_kernel(const float* __restrict__ x, float* __restrict__ out, int nrows, int ntiles)
{
    __shared__ uint4 w1s[512];
    __shared__ uint4 w3s[512];
    __shared__ float sp[192];
    __shared__ float bos[64];
    const int tid = threadIdx.x;
    {
        const uint4* s1 = (const uint4*)g_wp.w1;
        const uint4* s3 = (const uint4*)g_wp.w3;
        for (int i = tid; i < 512; i += 128) { w1s[i] = s1[i]; w3s[i] = s3[i]; }
        if (tid < 32) {
            sp[tid]       = g_wp.ab[tid];
            sp[32 + tid]  = g_wp.l1g[tid];
            sp[64 + tid]  = g_wp.l1b[tid];
            sp[96 + tid]  = g_wp.cb[tid];
            sp[128 + tid] = g_wp.l2g[tid];
            sp[160 + tid] = g_wp.l2b[tid];
        }
        if (tid < 64) bos[tid] = g_wp.bo[tid];
    }
    const int wid = tid >> 5, lane = tid & 31;
    const int g = lane >> 2, t = lane & 3;

    uint4 w2r[2][4];
#pragma unroll
    for (int kk = 0; kk < 2; kk++)
#pragma unroll
        for (int nn = 0; nn < 4; nn++) w2r[kk][nn] = g_wp.w2[kk][nn][lane];
    __syncthreads();

    const int stride = gridDim.x * 4;
    int tile = blockIdx.x * 4 + wid;
    if (tile >= ntiles) return;

    float4 xa[4], xb[4];
    loadx(x, tile, g, t, nrows, xa, xb);

    for (; tile < ntiles; tile += stride) {
        u32 ah[4][4], al[4][4];
#pragma unroll
        for (int kk = 0; kk < 4; kk++) {
            split2(xa[kk].x, xa[kk].y, ah[kk][0], al[kk][0]);
            split2(xb[kk].x, xb[kk].y, ah[kk][1], al[kk][1]);
            split2(xa[kk].z, xa[kk].w, ah[kk][2], al[kk][2]);
            split2(xb[kk].z, xb[kk].w, ah[kk][3], al[kk][3]);
        }
        if (tile + stride < ntiles) loadx(x, tile + stride, g, t, nrows, xa, xb);

        // GEMM1: [16x64]@[64x32]
        float acc[4][4];
#pragma unroll
        for (int nn = 0; nn < 4; nn++) {
            acc[nn][0] = acc[nn][1] = acc[nn][2] = acc[nn][3] = 0.f;
#pragma unroll
            for (int kk = 0; kk < 4; kk++) {
                uint4 w = w1s[(kk * 4 + nn) * 32 + lane];
                MMA(acc[nn], ah[kk][0], ah[kk][1], ah[kk][2], ah[kk][3], w.x, w.y);
                MMA(acc[nn], al[kk][0], al[kk][1], al[kk][2], al[kk][3], w.x, w.y);
                MMA(acc[nn], ah[kk][0], ah[kk][1], ah[kk][2], ah[kk][3], w.z, w.w);
            }
        }

        u32 a2h[2][4], a2l[2][4];
        ln_block(acc, sp + 0, sp + 32, sp + 64, t, a2h, a2l);

        // GEMM2: [16x32]@[32x32], weights in regs
        float acc2[4][4];
#pragma unroll
        for (int nn = 0; nn < 4; nn++) {
            acc2[nn][0] = acc2[nn][1] = acc2[nn][2] = acc2[nn][3] = 0.f;
#pragma unroll
            for (int kk = 0; kk < 2; kk++) {
                uint4 w = w2r[kk][nn];
                MMA(acc2[nn], a2h[kk][0], a2h[kk][1], a2h[kk][2], a2h[kk][3], w.x, w.y);
                MMA(acc2[nn], a2l[kk][0], a2l[kk][1], a2l[kk][2], a2l[kk][3], w.x, w.y);
                MMA(acc2[nn], a2h[kk][0], a2h[kk][1], a2h[kk][2], a2h[kk][3], w.z, w.w);
            }
        }

        u32 a3h[2][4], a3l[2][4];
        ln_block(acc2, sp + 96, sp + 128, sp + 160, t, a3h, a3l);

        // GEMM3: [16x32]@[32x64], store-permuted cols
        float acc3[8][4];
#pragma unroll
        for (int nn = 0; nn < 8; nn++) {
            acc3[nn][0] = acc3[nn][1] = acc3[nn][2] = acc3[nn][3] = 0.f;
#pragma unroll
            for (int kk = 0; kk < 2; kk++) {
                uint4 w = w3s[(kk * 8 + nn) * 32 + lane];
                MMA(acc3[nn], a3h[kk][0], a3h[kk][1], a3h[kk][2], a3h[kk][3], w.x, w.y);
                MMA(acc3[nn], a3l[kk][0], a3l[kk][1], a3l[kk][2], a3l[kk][3], w.x, w.y);
                MMA(acc3[nn], a3h[kk][0], a3h[kk][1], a3h[kk][2], a3h[kk][3], w.z, w.w);
            }
        }

        // + bo (packed ADD2), coalesced stores: instr j writes float4 @ col 16j+4t
        const int r0 = tile * 16 + g, r1 = r0 + 8;
        float* o0 = out + (size_t)r0 * 64;
        float* o1 = out + (size_t)r1 * 64;
        const bool v0 = r0 < nrows, v1 = r1 < nrows;
#pragma unroll
        for (int j = 0; j < 4; j++) {
            const u64 b01 = *(const u64*)(bos + 16 * j + 4 * t);
            const u64 b23 = *(const u64*)(bos + 16 * j + 4 * t + 2);
            if (v0) {
                u64 p = pk64(acc3[2 * j][0], acc3[2 * j][1]);
                u64 q = pk64(acc3[2 * j + 1][0], acc3[2 * j + 1][1]);
                ADD2(p, p, b01); ADD2(q, q, b23);
                float4 v;
                up64(v.x, v.y, p); up64(v.z, v.w, q);
                __stcs((float4*)(o0 + 16 * j + 4 * t), v);
            }
            if (v1) {
                u64 p = pk64(acc3[2 * j][2], acc3[2 * j][3]);
                u64 q = pk64(acc3[2 * j + 1][2], acc3[2 * j + 1][3]);
                ADD2(p, p, b01); ADD2(q, q, b23);
                float4 v;
                up64(v.x, v.y, p); up64(v.z, v.w, q);
                __stcs((float4*)(o1 + 16 * j + 4 * t), v);
            }
        }
    }
}

extern "C" void kernel_launch(void* const* d_in, const int* in_sizes, int n_in,
                              void* d_out, int out_size)
{
    const float* x   = (const float*)d_in[0];
    const float* w1  = (const float*)d_in[1];
    const float* b1  = (const float*)d_in[2];
    const float* wv1 = (const float*)d_in[7];
    const float* bv1 = (const float*)d_in[8];
    const float* g1  = (const float*)d_in[9];
    const float* l1g = (const float*)d_in[10];
    const float* l1b = (const float*)d_in[11];
    const float* w2  = (const float*)d_in[12];
    const float* b2  = (const float*)d_in[13];
    const float* wv2 = (const float*)d_in[18];
    const float* bv2 = (const float*)d_in[19];
    const float* g2  = (const float*)d_in[20];
    const float* l2g = (const float*)d_in[21];
    const float* l2b = (const float*)d_in[22];
    const float* wo  = (const float*)d_in[23];
    const float* bo  = (const float*)d_in[24];

    const int B = in_sizes[0] / 64;
    const int ntiles = (B + 15) / 16;

    prep_kernel<<<1, 256>>>(w1, b1, wv1, bv1, g1, l1g, l1b,
                            w2, b2, wv2, bv2, g2, l2g, l2b, wo, bo);

    int grid = 3 * 148;                       // 3 CTAs/SM x 4 warps, persistent
    int need = (ntiles + 3) / 4;
    if (grid > need) grid = need;
    fused_kernel<<<grid, 128>>>(x, (float*)d_out, B, ntiles);
}

// round 16
// speedup vs baseline: 1.1396x; 1.1396x over previous
#include <cuda_runtime.h>
#include <cuda_fp16.h>
#include <cstdint>

typedef uint32_t u32;
typedef unsigned long long u64;

__device__ __forceinline__ u64 pk64(float lo, float hi) {
    u64 r; asm("mov.b64 %0, {%1, %2};" : "=l"(r) : "f"(lo), "f"(hi)); return r;
}
__device__ __forceinline__ void up64(float& lo, float& hi, u64 v) {
    asm("mov.b64 {%0, %1}, %2;" : "=f"(lo), "=f"(hi) : "l"(v));
}
#define ADD2(d, a, b)    asm("add.rn.f32x2 %0, %1, %2;"     : "=l"(d) : "l"(a), "l"(b))
#define MUL2(d, a, b)    asm("mul.rn.f32x2 %0, %1, %2;"     : "=l"(d) : "l"(a), "l"(b))
#define FMA2(d, a, b, c) asm("fma.rn.f32x2 %0, %1, %2, %3;" : "=l"(d) : "l"(a), "l"(b), "l"(c))
#define C001X2  0x3C23D70A3C23D70Aull   // (0.01f, 0.01f)

// pack two floats into fp16x2 (a in low half)
__device__ __forceinline__ u32 pkh(float a, float b) {
    __half2 h = __floats2half2_rn(a, b);
    return *reinterpret_cast<u32*>(&h);
}
// fp16 2-term split: hp = fp16(a,b), lp = fp16(residual)
__device__ __forceinline__ void split2h(float a, float b, u32& hp, u32& lp) {
    __half2 h = __floats2half2_rn(a, b);
    float2 hf = __half22float2(h);
    __half2 l = __floats2half2_rn(a - hf.x, b - hf.y);
    hp = *reinterpret_cast<u32*>(&h);
    lp = *reinterpret_cast<u32*>(&l);
}

#define MMA(d, a0, a1, a2, a3, b0, b1)                                      \
    asm volatile("mma.sync.aligned.m16n8k16.row.col.f32.f16.f16.f32 "      \
                 "{%0,%1,%2,%3},{%4,%5,%6,%7},{%8,%9},{%0,%1,%2,%3};"       \
                 : "+f"((d)[0]), "+f"((d)[1]), "+f"((d)[2]), "+f"((d)[3])   \
                 : "r"(a0), "r"(a1), "r"(a2), "r"(a3), "r"(b0), "r"(b1))

// Per-lane weight fragments: uint2 = {b0, b1} fp16x2 (single-precision-quantized weights)
struct __align__(16) WBlob {
    uint2 w1[4][4][32];   // GEMM1, K-permuted for coalesced x loads
    uint2 w2[2][4][32];   // GEMM2, identity layout
    uint2 w3[2][8][32];   // GEMM3, N-permuted for coalesced stores
    float ab[32], cb[32], bo[64];
    float l1g[32], l1b[32], l2g[32], l2b[32];
};
__device__ WBlob g_wp;

// ---------------- prep ----------------
__global__ void prep_kernel(
    const float* __restrict__ w1,  const float* __restrict__ b1,
    const float* __restrict__ wv1, const float* __restrict__ bv1, const float* __restrict__ g1,
    const float* __restrict__ l1g, const float* __restrict__ l1b,
    const float* __restrict__ w2,  const float* __restrict__ b2,
    const float* __restrict__ wv2, const float* __restrict__ bv2, const float* __restrict__ g2,
    const float* __restrict__ l2g, const float* __restrict__ l2b,
    const float* __restrict__ wo,  const float* __restrict__ bo)
{
    __shared__ float Af[64 * 32];
    __shared__ float Cf[32 * 32];
    const int t = threadIdx.x;
    const float g1v = g1[0], g2v = g2[0];

    // fold T=1 attention (softmax == 1)
    for (int idx = t; idx < 64 * 32; idx += blockDim.x) {
        int i = idx >> 5, j = idx & 31;
        float s = 0.f;
        for (int m = 0; m < 32; m++) s += w1[i * 32 + m] * wv1[m * 32 + j];
        Af[idx] = w1[i * 32 + j] + g1v * s;
    }
    for (int idx = t; idx < 32 * 32; idx += blockDim.x) {
        int i = idx >> 5, j = idx & 31;
        float s = 0.f;
        for (int m = 0; m < 32; m++) s += w2[i * 32 + m] * wv2[m * 32 + j];
        Cf[idx] = w2[i * 32 + j] + g2v * s;
    }
    __syncthreads();

    // w1 frags: K-permuted
    for (int idx = t; idx < 4 * 4 * 32; idx += blockDim.x) {
        int kk = idx >> 7, nn = (idx >> 5) & 3, ln = idx & 31;
        int gg = ln >> 2, tt = ln & 3;
        int kb = 16 * kk + 4 * tt, n = 8 * nn + gg;
        uint2 v;
        v.x = pkh(Af[kb * 32 + n],       Af[(kb + 1) * 32 + n]);
        v.y = pkh(Af[(kb + 2) * 32 + n], Af[(kb + 3) * 32 + n]);
        g_wp.w1[kk][nn][ln] = v;
    }
    // w2 frags: identity
    for (int idx = t; idx < 2 * 4 * 32; idx += blockDim.x) {
        int kk = idx >> 7, nn = (idx >> 5) & 3, ln = idx & 31;
        int gg = ln >> 2, tt = ln & 3;
        int k0 = 16 * kk + 2 * tt, n = 8 * nn + gg;
        uint2 v;
        v.x = pkh(Cf[k0 * 32 + n],       Cf[(k0 + 1) * 32 + n]);
        v.y = pkh(Cf[(k0 + 8) * 32 + n], Cf[(k0 + 9) * 32 + n]);
        g_wp.w2[kk][nn][ln] = v;
    }
    // w3 frags: output-column permuted
    for (int idx = t; idx < 2 * 8 * 32; idx += blockDim.x) {
        int kk = idx >> 8, nn = (idx >> 5) & 7, ln = idx & 31;
        int gg = ln >> 2, tt = ln & 3;
        int k0 = 16 * kk + 2 * tt;
        int c = 16 * (nn >> 1) + 4 * (gg >> 1) + 2 * (nn & 1) + (gg & 1);
        uint2 v;
        v.x = pkh(wo[k0 * 64 + c],       wo[(k0 + 1) * 64 + c]);
        v.y = pkh(wo[(k0 + 8) * 64 + c], wo[(k0 + 9) * 64 + c]);
        g_wp.w3[kk][nn][ln] = v;
    }
    if (t < 32) {
        int j = t;
        float s1 = 0.f, s2 = 0.f;
        for (int m = 0; m < 32; m++) {
            s1 += b1[m] * wv1[m * 32 + j];
            s2 += b2[m] * wv2[m * 32 + j];
        }
        g_wp.ab[j] = b1[j] + g1v * (s1 + bv1[j]);
        g_wp.cb[j] = b2[j] + g2v * (s2 + bv2[j]);
        g_wp.l1g[j] = l1g[j]; g_wp.l1b[j] = l1b[j];
        g_wp.l2g[j] = l2g[j]; g_wp.l2b[j] = l2b[j];
    }
    if (t < 64) g_wp.bo[t] = bo[t];
}

// bias + LN + leaky on [16 x 32] block, f32x2-packed; emit fp16 2-term A frags
__device__ __forceinline__ void ln_block(float acc[4][4],
                                         const float* __restrict__ bias,
                                         const float* __restrict__ gg,
                                         const float* __restrict__ bb,
                                         int t, u32 oh[2][4], u32 ol[2][4])
{
    u64 p0[4], p1[4];
#pragma unroll
    for (int nn = 0; nn < 4; nn++) {
        const u64 bv = *(const u64*)(bias + 8 * nn + 2 * t);
        u64 a0 = pk64(acc[nn][0], acc[nn][1]);
        u64 a1 = pk64(acc[nn][2], acc[nn][3]);
        ADD2(p0[nn], a0, bv);
        ADD2(p1[nn], a1, bv);
    }
    u64 S0, S1, T0, T1, Q0, Q1;
    ADD2(S0, p0[0], p0[1]); ADD2(T0, p0[2], p0[3]); ADD2(S0, S0, T0);
    ADD2(S1, p1[0], p1[1]); ADD2(T1, p1[2], p1[3]); ADD2(S1, S1, T1);
    MUL2(Q0, p0[0], p0[0]); FMA2(Q0, p0[1], p0[1], Q0);
    FMA2(Q0, p0[2], p0[2], Q0); FMA2(Q0, p0[3], p0[3], Q0);
    MUL2(Q1, p1[0], p1[0]); FMA2(Q1, p1[1], p1[1], Q1);
    FMA2(Q1, p1[2], p1[2], Q1); FMA2(Q1, p1[3], p1[3], Q1);
    float al, ah, bl, bh;
    up64(al, ah, S0); float s0 = al + ah;
    up64(bl, bh, S1); float s1 = bl + bh;
    up64(al, ah, Q0); float q0 = al + ah;
    up64(bl, bh, Q1); float q1 = bl + bh;
#pragma unroll
    for (int m = 1; m < 4; m <<= 1) {
        s0 += __shfl_xor_sync(0xffffffffu, s0, m, 4);
        q0 += __shfl_xor_sync(0xffffffffu, q0, m, 4);
        s1 += __shfl_xor_sync(0xffffffffu, s1, m, 4);
        q1 += __shfl_xor_sync(0xffffffffu, q1, m, 4);
    }
    const float c = 1.0f / 32.0f;
    const float m0 = s0 * c, r0 = rsqrtf(fmaf(-m0, m0, q0 * c) + 1e-5f);
    const float m1 = s1 * c, r1 = rsqrtf(fmaf(-m1, m1, q1 * c) + 1e-5f);
    const u64 R0 = pk64(r0, r0), C0 = pk64(-m0 * r0, -m0 * r0);
    const u64 R1 = pk64(r1, r1), C1 = pk64(-m1 * r1, -m1 * r1);
    const u64 c001 = C001X2;

    float y[4][4];
#pragma unroll
    for (int nn = 0; nn < 4; nn++) {
        const u64 gv = *(const u64*)(gg + 8 * nn + 2 * t);
        const u64 bv = *(const u64*)(bb + 8 * nn + 2 * t);
        u64 n0, n1, y0, y1, z0, z1;
        FMA2(n0, p0[nn], R0, C0);
        FMA2(y0, n0, gv, bv);
        FMA2(n1, p1[nn], R1, C1);
        FMA2(y1, n1, gv, bv);
        MUL2(z0, y0, c001);
        MUL2(z1, y1, c001);
        float a, b, za, zb;
        up64(a, b, y0); up64(za, zb, z0);
        y[nn][0] = fmaxf(a, za); y[nn][1] = fmaxf(b, zb);
        up64(a, b, y1); up64(za, zb, z1);
        y[nn][2] = fmaxf(a, za); y[nn][3] = fmaxf(b, zb);
    }
#pragma unroll
    for (int kk = 0; kk < 2; kk++) {
        split2h(y[2 * kk][0],     y[2 * kk][1],     oh[kk][0], ol[kk][0]);
        split2h(y[2 * kk][2],     y[2 * kk][3],     oh[kk][1], ol[kk][1]);
        split2h(y[2 * kk + 1][0], y[2 * kk + 1][1], oh[kk][2], ol[kk][2]);
        split2h(y[2 * kk + 1][2], y[2 * kk + 1][3], oh[kk][3], ol[kk][3]);
    }
}

__device__ __forceinline__ void loadx(const float* __restrict__ x, int tile, int g, int t,
                                      int nrows, float4 xa[4], float4 xb[4])
{
    const int r0 = tile * 16 + g, r1 = r0 + 8;
    const float* b0 = x + (size_t)r0 * 64 + 4 * t;
    const float* b1 = x + (size_t)r1 * 64 + 4 * t;
    const bool v0 = r0 < nrows, v1 = r1 < nrows;
#pragma unroll
    for (int kk = 0; kk < 4; kk++) {
        xa[kk] = v0 ? __ldcs((const float4*)(b0 + 16 * kk)) : make_float4(0.f, 0.f, 0.f, 0.f);
        xb[kk] = v1 ? __ldcs((const float4*)(b1 + 16 * kk)) : make_float4(0.f, 0.f, 0.f, 0.f);
    }
}

// ---------------- fused kernel: fp16 2-term, R14 structure ----------------
__global__ void __launch_bounds__(128, 3)
fused_kernel(const float* __restrict__ x, float* __restrict__ out, int nrows, int ntiles)
{
    __shared__ uint2 w1s[512];            // GEMM1 frags (4 KB)
    __shared__ uint2 w3s[512];            // GEMM3 frags (4 KB)
    __shared__ float sp[192];
    __shared__ float bos[64];
    const int tid = threadIdx.x;
    {
        const uint2* s1 = (const uint2*)g_wp.w1;
        const uint2* s3 = (const uint2*)g_wp.w3;
        for (int i = tid; i < 512; i += 128) { w1s[i] = s1[i]; w3s[i] = s3[i]; }
        if (tid < 32) {
            sp[tid]       = g_wp.ab[tid];
            sp[32 + tid]  = g_wp.l1g[tid];
            sp[64 + tid]  = g_wp.l1b[tid];
            sp[96 + tid]  = g_wp.cb[tid];
            sp[128 + tid] = g_wp.l2g[tid];
            sp[160 + tid] = g_wp.l2b[tid];
        }
        if (tid < 64) bos[tid] = g_wp.bo[tid];
    }
    const int wid = tid >> 5, lane = tid & 31;
    const int g = lane >> 2, t = lane & 3;

    // GEMM2 weights persistent in registers (16 regs)
    uint2 w2r[2][4];
#pragma unroll
    for (int kk = 0; kk < 2; kk++)
#pragma unroll
        for (int nn = 0; nn < 4; nn++) w2r[kk][nn] = g_wp.w2[kk][nn][lane];
    __syncthreads();

    const int stride = gridDim.x * 4;
    int tile = blockIdx.x * 4 + wid;
    if (tile >= ntiles) return;

    float4 xa[4], xb[4];
    loadx(x, tile, g, t, nrows, xa, xb);

    for (; tile < ntiles; tile += stride) {
        u32 ah[4][4], al[4][4];
#pragma unroll
        for (int kk = 0; kk < 4; kk++) {
            split2h(xa[kk].x, xa[kk].y, ah[kk][0], al[kk][0]);
            split2h(xb[kk].x, xb[kk].y, ah[kk][1], al[kk][1]);
            split2h(xa[kk].z, xa[kk].w, ah[kk][2], al[kk][2]);
            split2h(xb[kk].z, xb[kk].w, ah[kk][3], al[kk][3]);
        }
        if (tile + stride < ntiles) loadx(x, tile + stride, g, t, nrows, xa, xb);

        // GEMM1: [16x64]@[64x32], 2 MMAs per kfrag
        float acc[4][4];
#pragma unroll
        for (int nn = 0; nn < 4; nn++) {
            acc[nn][0] = acc[nn][1] = acc[nn][2] = acc[nn][3] = 0.f;
#pragma unroll
            for (int kk = 0; kk < 4; kk++) {
                uint2 w = w1s[(kk * 4 + nn) * 32 + lane];
                MMA(acc[nn], ah[kk][0], ah[kk][1], ah[kk][2], ah[kk][3], w.x, w.y);
                MMA(acc[nn], al[kk][0], al[kk][1], al[kk][2], al[kk][3], w.x, w.y);
            }
        }

        u32 a2h[2][4], a2l[2][4];
        ln_block(acc, sp + 0, sp + 32, sp + 64, t, a2h, a2l);

        // GEMM2: [16x32]@[32x32], weights in regs
        float acc2[4][4];
#pragma unroll
        for (int nn = 0; nn < 4; nn++) {
            acc2[nn][0] = acc2[nn][1] = acc2[nn][2] = acc2[nn][3] = 0.f;
#pragma unroll
            for (int kk = 0; kk < 2; kk++) {
                uint2 w = w2r[kk][nn];
                MMA(acc2[nn], a2h[kk][0], a2h[kk][1], a2h[kk][2], a2h[kk][3], w.x, w.y);
                MMA(acc2[nn], a2l[kk][0], a2l[kk][1], a2l[kk][2], a2l[kk][3], w.x, w.y);
            }
        }

        u32 a3h[2][4], a3l[2][4];
        ln_block(acc2, sp + 96, sp + 128, sp + 160, t, a3h, a3l);

        // GEMM3: [16x32]@[32x64], store-permuted cols
        float acc3[8][4];
#pragma unroll
        for (int nn = 0; nn < 8; nn++) {
            acc3[nn][0] = acc3[nn][1] = acc3[nn][2] = acc3[nn][3] = 0.f;
#pragma unroll
            for (int kk = 0; kk < 2; kk++) {
                uint2 w = w3s[(kk * 8 + nn) * 32 + lane];
                MMA(acc3[nn], a3h[kk][0], a3h[kk][1], a3h[kk][2], a3h[kk][3], w.x, w.y);
                MMA(acc3[nn], a3l[kk][0], a3l[kk][1], a3l[kk][2], a3l[kk][3], w.x, w.y);
            }
        }

        // + bo (packed ADD2), coalesced stores: instr j writes float4 @ col 16j+4t
        const int r0 = tile * 16 + g, r1 = r0 + 8;
        float* o0 = out + (size_t)r0 * 64;
        float* o1 = out + (size_t)r1 * 64;
        const bool v0 = r0 < nrows, v1 = r1 < nrows;
#pragma unroll
        for (int j = 0; j < 4; j++) {
            const u64 b01 = *(const u64*)(bos + 16 * j + 4 * t);
            const u64 b23 = *(const u64*)(bos + 16 * j + 4 * t + 2);
            if (v0) {
                u64 p = pk64(acc3[2 * j][0], acc3[2 * j][1]);
                u64 q = pk64(acc3[2 * j + 1][0], acc3[2 * j + 1][1]);
                ADD2(p, p, b01); ADD2(q, q, b23);
                float4 v;
                up64(v.x, v.y, p); up64(v.z, v.w, q);
                __stcs((float4*)(o0 + 16 * j + 4 * t), v);
            }
            if (v1) {
                u64 p = pk64(acc3[2 * j][2], acc3[2 * j][3]);
                u64 q = pk64(acc3[2 * j + 1][2], acc3[2 * j + 1][3]);
                ADD2(p, p, b01); ADD2(q, q, b23);
                float4 v;
                up64(v.x, v.y, p); up64(v.z, v.w, q);
                __stcs((float4*)(o1 + 16 * j + 4 * t), v);
            }
        }
    }
}

extern "C" void kernel_launch(void* const* d_in, const int* in_sizes, int n_in,
                              void* d_out, int out_size)
{
    const float* x   = (const float*)d_in[0];
    const float* w1  = (const float*)d_in[1];
    const float* b1  = (const float*)d_in[2];
    const float* wv1 = (const float*)d_in[7];
    const float* bv1 = (const float*)d_in[8];
    const float* g1  = (const float*)d_in[9];
    const float* l1g = (const float*)d_in[10];
    const float* l1b = (const float*)d_in[11];
    const float* w2  = (const float*)d_in[12];
    const float* b2  = (const float*)d_in[13];
    const float* wv2 = (const float*)d_in[18];
    const float* bv2 = (const float*)d_in[19];
    const float* g2  = (const float*)d_in[20];
    const float* l2g = (const float*)d_in[21];
    const float* l2b = (const float*)d_in[22];
    const float* wo  = (const float*)d_in[23];
    const float* bo  = (const float*)d_in[24];

    const int B = in_sizes[0] / 64;
    const int ntiles = (B + 15) / 16;

    prep_kernel<<<1, 256>>>(w1, b1, wv1, bv1, g1, l1g, l1b,
                            w2, b2, wv2, bv2, g2, l2g, l2b, wo, bo);

    int grid = 3 * 148;                       // 3 CTAs/SM x 4 warps, persistent
    int need = (ntiles + 3) / 4;
    if (grid > need) grid = need;
    fused_kernel<<<grid, 128>>>(x, (float*)d_out, B, ntiles);
}

// round 17
// speedup vs baseline: 1.1871x; 1.0417x over previous
#include <cuda_runtime.h>
#include <cuda_fp16.h>
#include <cstdint>

typedef uint32_t u32;
typedef unsigned long long u64;

__device__ __forceinline__ u64 pk64(float lo, float hi) {
    u64 r; asm("mov.b64 %0, {%1, %2};" : "=l"(r) : "f"(lo), "f"(hi)); return r;
}
__device__ __forceinline__ void up64(float& lo, float& hi, u64 v) {
    asm("mov.b64 {%0, %1}, %2;" : "=f"(lo), "=f"(hi) : "l"(v));
}
#define ADD2(d, a, b)    asm("add.rn.f32x2 %0, %1, %2;"     : "=l"(d) : "l"(a), "l"(b))
#define MUL2(d, a, b)    asm("mul.rn.f32x2 %0, %1, %2;"     : "=l"(d) : "l"(a), "l"(b))
#define FMA2(d, a, b, c) asm("fma.rn.f32x2 %0, %1, %2, %3;" : "=l"(d) : "l"(a), "l"(b), "l"(c))
#define C001X2  0x3C23D70A3C23D70Aull   // (0.01f, 0.01f)

__device__ __forceinline__ u32 pkh(float a, float b) {
    __half2 h = __floats2half2_rn(a, b);
    return *reinterpret_cast<u32*>(&h);
}
__device__ __forceinline__ void split2h(float a, float b, u32& hp, u32& lp) {
    __half2 h = __floats2half2_rn(a, b);
    float2 hf = __half22float2(h);
    __half2 l = __floats2half2_rn(a - hf.x, b - hf.y);
    hp = *reinterpret_cast<u32*>(&h);
    lp = *reinterpret_cast<u32*>(&l);
}

#define MMA(d, a0, a1, a2, a3, b0, b1)                                      \
    asm volatile("mma.sync.aligned.m16n8k16.row.col.f32.f16.f16.f32 "      \
                 "{%0,%1,%2,%3},{%4,%5,%6,%7},{%8,%9},{%0,%1,%2,%3};"       \
                 : "+f"((d)[0]), "+f"((d)[1]), "+f"((d)[2]), "+f"((d)[3])   \
                 : "r"(a0), "r"(a1), "r"(a2), "r"(a3), "r"(b0), "r"(b1))

// Per-lane weight fragments: uint2 = {b0, b1} fp16x2
struct __align__(16) WBlob {
    uint2 w1[4][4][32];
    uint2 w2[2][4][32];
    uint2 w3[2][8][32];
    float ab[32], cb[32], bo[64];
    float l1g[32], l1b[32], l2g[32], l2b[32];
};
__device__ WBlob g_wp;

// ---------------- fast prep: smem-staged, 512 threads ----------------
__global__ void __launch_bounds__(512)
prep_kernel(
    const float* __restrict__ w1,  const float* __restrict__ b1,
    const float* __restrict__ wv1, const float* __restrict__ bv1, const float* __restrict__ g1,
    const float* __restrict__ l1g, const float* __restrict__ l1b,
    const float* __restrict__ w2,  const float* __restrict__ b2,
    const float* __restrict__ wv2, const float* __restrict__ bv2, const float* __restrict__ g2,
    const float* __restrict__ l2g, const float* __restrict__ l2b,
    const float* __restrict__ wo,  const float* __restrict__ bo)
{
    __shared__ float sw1[2048];   // w1  [64,32]
    __shared__ float sv1[1024];   // wv1 [32,32]
    __shared__ float sw2[1024];   // w2  [32,32]
    __shared__ float sv2[1024];   // wv2 [32,32]
    __shared__ float swo[2048];   // wo  [32,64]
    __shared__ float Af[2048];
    __shared__ float Cf[1024];
    const int t = threadIdx.x;
    const float g1v = g1[0], g2v = g2[0];

    for (int i = t; i < 2048; i += 512) { sw1[i] = w1[i]; swo[i] = wo[i]; }
    for (int i = t; i < 1024; i += 512) { sv1[i] = wv1[i]; sw2[i] = w2[i]; sv2[i] = wv2[i]; }
    __syncthreads();

    // Af = w1 @ (I + g1*wv1); Cf = w2 @ (I + g2*wv2) — same m-ascending order
    for (int idx = t; idx < 2048; idx += 512) {
        int i = idx >> 5, j = idx & 31;
        float s = 0.f;
#pragma unroll
        for (int m = 0; m < 32; m++) s += sw1[i * 32 + m] * sv1[m * 32 + j];
        Af[idx] = sw1[i * 32 + j] + g1v * s;
    }
    for (int idx = t; idx < 1024; idx += 512) {
        int i = idx >> 5, j = idx & 31;
        float s = 0.f;
#pragma unroll
        for (int m = 0; m < 32; m++) s += sw2[i * 32 + m] * sv2[m * 32 + j];
        Cf[idx] = sw2[i * 32 + j] + g2v * s;
    }
    __syncthreads();

    for (int idx = t; idx < 512; idx += 512) {
        int kk = idx >> 7, nn = (idx >> 5) & 3, ln = idx & 31;
        int gg = ln >> 2, tt = ln & 3;
        int kb = 16 * kk + 4 * tt, n = 8 * nn + gg;
        uint2 v;
        v.x = pkh(Af[kb * 32 + n],       Af[(kb + 1) * 32 + n]);
        v.y = pkh(Af[(kb + 2) * 32 + n], Af[(kb + 3) * 32 + n]);
        g_wp.w1[kk][nn][ln] = v;
    }
    for (int idx = t; idx < 256; idx += 512) {
        int kk = idx >> 7, nn = (idx >> 5) & 3, ln = idx & 31;
        int gg = ln >> 2, tt = ln & 3;
        int k0 = 16 * kk + 2 * tt, n = 8 * nn + gg;
        uint2 v;
        v.x = pkh(Cf[k0 * 32 + n],       Cf[(k0 + 1) * 32 + n]);
        v.y = pkh(Cf[(k0 + 8) * 32 + n], Cf[(k0 + 9) * 32 + n]);
        g_wp.w2[kk][nn][ln] = v;
    }
    for (int idx = t; idx < 512; idx += 512) {
        int kk = idx >> 8, nn = (idx >> 5) & 7, ln = idx & 31;
        int gg = ln >> 2, tt = ln & 3;
        int k0 = 16 * kk + 2 * tt;
        int c = 16 * (nn >> 1) + 4 * (gg >> 1) + 2 * (nn & 1) + (gg & 1);
        uint2 v;
        v.x = pkh(swo[k0 * 64 + c],       swo[(k0 + 1) * 64 + c]);
        v.y = pkh(swo[(k0 + 8) * 64 + c], swo[(k0 + 9) * 64 + c]);
        g_wp.w3[kk][nn][ln] = v;
    }
    if (t < 32) {
        int j = t;
        float s1 = 0.f, s2 = 0.f;
#pragma unroll
        for (int m = 0; m < 32; m++) {
            s1 += b1[m] * sv1[m * 32 + j];
            s2 += b2[m] * sv2[m * 32 + j];
        }
        g_wp.ab[j] = b1[j] + g1v * (s1 + bv1[j]);
        g_wp.cb[j] = b2[j] + g2v * (s2 + bv2[j]);
        g_wp.l1g[j] = l1g[j]; g_wp.l1b[j] = l1b[j];
        g_wp.l2g[j] = l2g[j]; g_wp.l2b[j] = l2b[j];
    }
    if (t < 64) g_wp.bo[t] = bo[t];
}

// bias + LN + leaky on [16 x 32] block, f32x2-packed; emit fp16 2-term A frags
__device__ __forceinline__ void ln_block(float acc[4][4],
                                         const float* __restrict__ bias,
                                         const float* __restrict__ gg,
                                         const float* __restrict__ bb,
                                         int t, u32 oh[2][4], u32 ol[2][4])
{
    u64 p0[4], p1[4];
#pragma unroll
    for (int nn = 0; nn < 4; nn++) {
        const u64 bv = *(const u64*)(bias + 8 * nn + 2 * t);
        u64 a0 = pk64(acc[nn][0], acc[nn][1]);
        u64 a1 = pk64(acc[nn][2], acc[nn][3]);
        ADD2(p0[nn], a0, bv);
        ADD2(p1[nn], a1, bv);
    }
    u64 S0, S1, T0, T1, Q0, Q1;
    ADD2(S0, p0[0], p0[1]); ADD2(T0, p0[2], p0[3]); ADD2(S0, S0, T0);
    ADD2(S1, p1[0], p1[1]); ADD2(T1, p1[2], p1[3]); ADD2(S1, S1, T1);
    MUL2(Q0, p0[0], p0[0]); FMA2(Q0, p0[1], p0[1], Q0);
    FMA2(Q0, p0[2], p0[2], Q0); FMA2(Q0, p0[3], p0[3], Q0);
    MUL2(Q1, p1[0], p1[0]); FMA2(Q1, p1[1], p1[1], Q1);
    FMA2(Q1, p1[2], p1[2], Q1); FMA2(Q1, p1[3], p1[3], Q1);
    float al, ah, bl, bh;
    up64(al, ah, S0); float s0 = al + ah;
    up64(bl, bh, S1); float s1 = bl + bh;
    up64(al, ah, Q0); float q0 = al + ah;
    up64(bl, bh, Q1); float q1 = bl + bh;
#pragma unroll
    for (int m = 1; m < 4; m <<= 1) {
        s0 += __shfl_xor_sync(0xffffffffu, s0, m, 4);
        q0 += __shfl_xor_sync(0xffffffffu, q0, m, 4);
        s1 += __shfl_xor_sync(0xffffffffu, s1, m, 4);
        q1 += __shfl_xor_sync(0xffffffffu, q1, m, 4);
    }
    const float c = 1.0f / 32.0f;
    const float m0 = s0 * c, r0 = rsqrtf(fmaf(-m0, m0, q0 * c) + 1e-5f);
    const float m1 = s1 * c, r1 = rsqrtf(fmaf(-m1, m1, q1 * c) + 1e-5f);
    const u64 R0 = pk64(r0, r0), C0 = pk64(-m0 * r0, -m0 * r0);
    const u64 R1 = pk64(r1, r1), C1 = pk64(-m1 * r1, -m1 * r1);
    const u64 c001 = C001X2;

    float y[4][4];
#pragma unroll
    for (int nn = 0; nn < 4; nn++) {
        const u64 gv = *(const u64*)(gg + 8 * nn + 2 * t);
        const u64 bv = *(const u64*)(bb + 8 * nn + 2 * t);
        u64 n0, n1, y0, y1, z0, z1;
        FMA2(n0, p0[nn], R0, C0);
        FMA2(y0, n0, gv, bv);
        FMA2(n1, p1[nn], R1, C1);
        FMA2(y1, n1, gv, bv);
        MUL2(z0, y0, c001);
        MUL2(z1, y1, c001);
        float a, b, za, zb;
        up64(a, b, y0); up64(za, zb, z0);
        y[nn][0] = fmaxf(a, za); y[nn][1] = fmaxf(b, zb);
        up64(a, b, y1); up64(za, zb, z1);
        y[nn][2] = fmaxf(a, za); y[nn][3] = fmaxf(b, zb);
    }
#pragma unroll
    for (int kk = 0; kk < 2; kk++) {
        split2h(y[2 * kk][0],     y[2 * kk][1],     oh[kk][0], ol[kk][0]);
        split2h(y[2 * kk][2],     y[2 * kk][3],     oh[kk][1], ol[kk][1]);
        split2h(y[2 * kk + 1][0], y[2 * kk + 1][1], oh[kk][2], ol[kk][2]);
        split2h(y[2 * kk + 1][2], y[2 * kk + 1][3], oh[kk][3], ol[kk][3]);
    }
}

__device__ __forceinline__ void loadx(const float* __restrict__ x, int tile, int g, int t,
                                      int nrows, float4 xa[4], float4 xb[4])
{
    const int r0 = tile * 16 + g, r1 = r0 + 8;
    const float* b0 = x + (size_t)r0 * 64 + 4 * t;
    const float* b1 = x + (size_t)r1 * 64 + 4 * t;
    const bool v0 = r0 < nrows, v1 = r1 < nrows;
#pragma unroll
    for (int kk = 0; kk < 4; kk++) {
        xa[kk] = v0 ? __ldcs((const float4*)(b0 + 16 * kk)) : make_float4(0.f, 0.f, 0.f, 0.f);
        xb[kk] = v1 ? __ldcs((const float4*)(b1 + 16 * kk)) : make_float4(0.f, 0.f, 0.f, 0.f);
    }
}

// ---------------- fused kernel: fp16 2-term, all weights in smem, 4 CTAs/SM ----------------
__global__ void __launch_bounds__(128, 4)
fused_kernel(const float* __restrict__ x, float* __restrict__ out, int nrows, int ntiles)
{
    __shared__ uint2 w1s[512];            // GEMM1 frags (4 KB)
    __shared__ uint2 w2s[256];            // GEMM2 frags (2 KB)
    __shared__ uint2 w3s[512];            // GEMM3 frags (4 KB)
    __shared__ float sp[192];
    __shared__ float bos[64];
    const int tid = threadIdx.x;
    {
        const uint2* s1 = (const uint2*)g_wp.w1;
        const uint2* s2 = (const uint2*)g_wp.w2;
        const uint2* s3 = (const uint2*)g_wp.w3;
        for (int i = tid; i < 512; i += 128) { w1s[i] = s1[i]; w3s[i] = s3[i]; }
        for (int i = tid; i < 256; i += 128) w2s[i] = s2[i];
        if (tid < 32) {
            sp[tid]       = g_wp.ab[tid];
            sp[32 + tid]  = g_wp.l1g[tid];
            sp[64 + tid]  = g_wp.l1b[tid];
            sp[96 + tid]  = g_wp.cb[tid];
            sp[128 + tid] = g_wp.l2g[tid];
            sp[160 + tid] = g_wp.l2b[tid];
        }
        if (tid < 64) bos[tid] = g_wp.bo[tid];
    }
    const int wid = tid >> 5, lane = tid & 31;
    const int g = lane >> 2, t = lane & 3;
    __syncthreads();

    const int stride = gridDim.x * 4;
    int tile = blockIdx.x * 4 + wid;
    if (tile >= ntiles) return;

    float4 xa[4], xb[4];
    loadx(x, tile, g, t, nrows, xa, xb);

    for (; tile < ntiles; tile += stride) {
        u32 ah[4][4], al[4][4];
#pragma unroll
        for (int kk = 0; kk < 4; kk++) {
            split2h(xa[kk].x, xa[kk].y, ah[kk][0], al[kk][0]);
            split2h(xb[kk].x, xb[kk].y, ah[kk][1], al[kk][1]);
            split2h(xa[kk].z, xa[kk].w, ah[kk][2], al[kk][2]);
            split2h(xb[kk].z, xb[kk].w, ah[kk][3], al[kk][3]);
        }
        if (tile + stride < ntiles) loadx(x, tile + stride, g, t, nrows, xa, xb);

        // GEMM1: [16x64]@[64x32]
        float acc[4][4];
#pragma unroll
        for (int nn = 0; nn < 4; nn++) {
            acc[nn][0] = acc[nn][1] = acc[nn][2] = acc[nn][3] = 0.f;
#pragma unroll
            for (int kk = 0; kk < 4; kk++) {
                uint2 w = w1s[(kk * 4 + nn) * 32 + lane];
                MMA(acc[nn], ah[kk][0], ah[kk][1], ah[kk][2], ah[kk][3], w.x, w.y);
                MMA(acc[nn], al[kk][0], al[kk][1], al[kk][2], al[kk][3], w.x, w.y);
            }
        }

        u32 a2h[2][4], a2l[2][4];
        ln_block(acc, sp + 0, sp + 32, sp + 64, t, a2h, a2l);

        // GEMM2: [16x32]@[32x32]
        float acc2[4][4];
#pragma unroll
        for (int nn = 0; nn < 4; nn++) {
            acc2[nn][0] = acc2[nn][1] = acc2[nn][2] = acc2[nn][3] = 0.f;
#pragma unroll
            for (int kk = 0; kk < 2; kk++) {
                uint2 w = w2s[(kk * 4 + nn) * 32 + lane];
                MMA(acc2[nn], a2h[kk][0], a2h[kk][1], a2h[kk][2], a2h[kk][3], w.x, w.y);
                MMA(acc2[nn], a2l[kk][0], a2l[kk][1], a2l[kk][2], a2l[kk][3], w.x, w.y);
            }
        }

        u32 a3h[2][4], a3l[2][4];
        ln_block(acc2, sp + 96, sp + 128, sp + 160, t, a3h, a3l);

        // GEMM3: [16x32]@[32x64], store-permuted cols
        float acc3[8][4];
#pragma unroll
        for (int nn = 0; nn < 8; nn++) {
            acc3[nn][0] = acc3[nn][1] = acc3[nn][2] = acc3[nn][3] = 0.f;
#pragma unroll
            for (int kk = 0; kk < 2; kk++) {
                uint2 w = w3s[(kk * 8 + nn) * 32 + lane];
                MMA(acc3[nn], a3h[kk][0], a3h[kk][1], a3h[kk][2], a3h[kk][3], w.x, w.y);
                MMA(acc3[nn], a3l[kk][0], a3l[kk][1], a3l[kk][2], a3l[kk][3], w.x, w.y);
            }
        }

        // + bo (packed ADD2), coalesced stores
        const int r0 = tile * 16 + g, r1 = r0 + 8;
        float* o0 = out + (size_t)r0 * 64;
        float* o1 = out + (size_t)r1 * 64;
        const bool v0 = r0 < nrows, v1 = r1 < nrows;
#pragma unroll
        for (int j = 0; j < 4; j++) {
            const u64 b01 = *(const u64*)(bos + 16 * j + 4 * t);
            const u64 b23 = *(const u64*)(bos + 16 * j + 4 * t + 2);
            if (v0) {
                u64 p = pk64(acc3[2 * j][0], acc3[2 * j][1]);
                u64 q = pk64(acc3[2 * j + 1][0], acc3[2 * j + 1][1]);
                ADD2(p, p, b01); ADD2(q, q, b23);
                float4 v;
                up64(v.x, v.y, p); up64(v.z, v.w, q);
                __stcs((float4*)(o0 + 16 * j + 4 * t), v);
            }
            if (v1) {
                u64 p = pk64(acc3[2 * j][2], acc3[2 * j][3]);
                u64 q = pk64(acc3[2 * j + 1][2], acc3[2 * j + 1][3]);
                ADD2(p, p, b01); ADD2(q, q, b23);
                float4 v;
                up64(v.x, v.y, p); up64(v.z, v.w, q);
                __stcs((float4*)(o1 + 16 * j + 4 * t), v);
            }
        }
    }
}

extern "C" void kernel_launch(void* const* d_in, const int* in_sizes, int n_in,
                              void* d_out, int out_size)
{
    const float* x   = (const float*)d_in[0];
    const float* w1  = (const float*)d_in[1];
    const float* b1  = (const float*)d_in[2];
    const float* wv1 = (const float*)d_in[7];
    const float* bv1 = (const float*)d_in[8];
    const float* g1  = (const float*)d_in[9];
    const float* l1g = (const float*)d_in[10];
    const float* l1b = (const float*)d_in[11];
    const float* w2  = (const float*)d_in[12];
    const float* b2  = (const float*)d_in[13];
    const float* wv2 = (const float*)d_in[18];
    const float* bv2 = (const float*)d_in[19];
    const float* g2  = (const float*)d_in[20];
    const float* l2g = (const float*)d_in[21];
    const float* l2b = (const float*)d_in[22];
    const float* wo  = (const float*)d_in[23];
    const float* bo  = (const float*)d_in[24];

    const int B = in_sizes[0] / 64;
    const int ntiles = (B + 15) / 16;

    prep_kernel<<<1, 512>>>(w1, b1, wv1, bv1, g1, l1g, l1b,
                            w2, b2, wv2, bv2, g2, l2g, l2b, wo, bo);

    int grid = 4 * 148;                       // 4 CTAs/SM x 4 warps, persistent
    int need = (ntiles + 3) / 4;
    if (grid > need) grid = need;
    fused_kernel<<<grid, 128>>>(x, (float*)d_out, B, ntiles);
}